// round 10
// baseline (speedup 1.0000x reference)
#include <cuda_runtime.h>
#include <cuda_bf16.h>

// ZBL basis: per-edge screened Coulomb repulsion with polynomial cutoff,
// scatter-summed into receiver nodes.
//
// Inputs (metadata order):
//   d_in[0]: x               float32 [E, 1]   (E = 3,200,000)
//   d_in[1]: node_attrs      float32 [N, 10]  (N = 100,000)
//   d_in[2]: edge_index      int32   [2, E]
//   d_in[3]: atomic_numbers  int32   [10]
//   d_in[4]: covalent_radii  float32 [119]
// Output: V_ZBL float32 [N]
//
// Three-stage pipeline:
//  1) node_prep: argmax -> nibble-packed element table; zero output.
//  2) filter:    stream all edges, gather element nibbles, cutoff test,
//                compact survivors (x, pairidx<<24 | r) into PER-WARP private
//                scratch regions (ballot/popc compaction: no atomics/syncs).
//  3) scatter:   stream survivors only (~50%), LUT via pair idx (no gathers),
//                math, UNCONDITIONAL fully-active red.global.add.
// Rationale (R9 evidence): spread REDs cost full wavefronts regardless of
// predication; compaction halves warp-RED count, math, MUFU, LUT work.

#define MAX_NODES 100352            // >= N, even, multiple of 32
#define PACKED_N  (MAX_NODES / 2)   // nibble-packed element table bytes
#define N_ELEMS   10
#define NPAIR     (N_ELEMS * N_ELEMS)
#define NT        512
#define EDGE_GRID 444               // 3 blocks/SM x 148 SMs, one wave
#define SURV_CAP  3600000           // >= W * region for E=3.2M

__device__ unsigned char g_e4[PACKED_N];     // 2 nodes/byte: elem nibbles
__device__ uint2         g_surv[SURV_CAP];   // survivor (x, idx<<24|r)
__device__ unsigned int  g_wcnt[EDGE_GRID * NT / 32];

__device__ __forceinline__ float ex2f(float a) {
    float r; asm("ex2.approx.f32 %0, %1;" : "=f"(r) : "f"(a)); return r;
}
__device__ __forceinline__ float frcpf(float a) {
    float r; asm("rcp.approx.f32 %0, %1;" : "=f"(r) : "f"(a)); return r;
}

// ---------------------------------------------------------------------------
// Stage 1: node prep (two nodes per thread -> one packed byte), zero output.
// ---------------------------------------------------------------------------
__global__ void node_prep_kernel(const float* __restrict__ attrs,
                                 float* __restrict__ out,
                                 int n_nodes, int out_n) {
    __shared__ float s[512 * N_ELEMS];
    int base = blockIdx.x * 512;
    int nloc = n_nodes - base;
    if (nloc > 512) nloc = 512;
    if (nloc > 0) {
        int total = nloc * N_ELEMS;
        const float* src = attrs + (size_t)base * N_ELEMS;
        int nv4 = total >> 2;
        const float4* s4 = (const float4*)src;
        float4* d4 = (float4*)s;
        for (int k = threadIdx.x; k < nv4; k += 256) d4[k] = s4[k];
        for (int k = (nv4 << 2) + threadIdx.x; k < total; k += 256)
            s[k] = src[k];
    }
    __syncthreads();

    int t = threadIdx.x;
    int n0 = 2 * t, n1 = 2 * t + 1;
    unsigned char packed = 0;
#pragma unroll
    for (int half = 0; half < 2; half++) {
        int nl = half ? n1 : n0;
        if (nl < nloc) {
            const float* a = s + nl * N_ELEMS;
            int best = 0;
            float bv = a[0];
#pragma unroll
            for (int j = 1; j < N_ELEMS; j++) {
                float v = a[j];
                if (v > bv) { bv = v; best = j; }
            }
            packed |= (unsigned char)(best << (half * 4));
        }
    }
    if (n0 < nloc) g_e4[(base >> 1) + t] = packed;

    int o0 = base + n0, o1 = base + n1;
    if (o0 < out_n) out[o0] = 0.0f;
    if (o1 < out_n) out[o1] = 0.0f;
}

// ---------------------------------------------------------------------------
// Stage 2: filter + per-warp compaction.
// ---------------------------------------------------------------------------
__device__ __forceinline__ void filt_one(
    int s, int r, float xi, int lane,
    const unsigned char* __restrict__ s_e4,
    const float* __restrict__ s_irm,
    unsigned int rbase, unsigned int& base)
{
    int eu = (s_e4[s >> 1] >> ((s & 1) << 2)) & 15;
    int ev = (s_e4[r >> 1] >> ((r & 1) << 2)) & 15;
    int idx = eu * N_ELEMS + ev;
    float irm = s_irm[(idx << 5) + lane];          // 32x repl: conflict-free
    bool p = (xi * irm) < 1.0f;
    unsigned int ball = __ballot_sync(0xffffffffu, p);
    if (p) {
        unsigned int excl = __popc(ball & ((1u << lane) - 1u));
        g_surv[rbase + base + excl] =
            make_uint2(__float_as_uint(xi),
                       ((unsigned int)idx << 24) | (unsigned int)r);
    }
    base += __popc(ball);
}

__global__ void __launch_bounds__(NT, 3)
filter_kernel(const float* __restrict__ x,
              const int* __restrict__ ei,
              const int* __restrict__ atomic_numbers,
              const float* __restrict__ radii_g,
              int n_edges, int n_nodes) {
    extern __shared__ char smem[];
    float* s_irm = (float*)smem;                       // NPAIR*32 floats
    unsigned char* s_e4 = (unsigned char*)(s_irm + NPAIR * 32);

    int tid = threadIdx.x, lane = tid & 31;

    if (tid < NPAIR) {
        int i = tid / N_ELEMS, j = tid % N_ELEMS;
        int Zi = atomic_numbers[i], Zj = atomic_numbers[j];
        float irm = 1.0f / (radii_g[Zi] + radii_g[Zj]);
        int b = tid << 5;
#pragma unroll
        for (int c = 0; c < 32; c++) s_irm[b + c] = irm;
    }
    {
        const uint4* ge = (const uint4*)g_e4;
        uint4* se = (uint4*)s_e4;
        int nvec = (((n_nodes + 1) >> 1) + 15) >> 4;
        for (int w0 = tid; w0 < nvec; w0 += NT) se[w0] = ge[w0];
    }
    __syncthreads();

    int n4 = n_edges >> 2;
    int W = (gridDim.x * NT) >> 5;
    int w = (blockIdx.x * NT + tid) >> 5;
    int vpw = (n4 + W - 1) / W;             // vec4 iters per warp
    int region = vpw * 4 + 32;              // +32 headroom for scalar tail
    unsigned int rbase = (unsigned int)w * (unsigned int)region;

    const int4*   si = (const int4*)ei;
    const int4*   ri = (const int4*)(ei + n_edges);
    const float4* x4 = (const float4*)x;

    int gstart = w * vpw;
    int gend = gstart + vpw; if (gend > n4) gend = n4;
    unsigned int base = 0;

    for (int g0 = gstart; g0 < gend; g0 += 32) {
        int g = g0 + lane;
        bool act = g < gend;
        int4 ss   = act ? si[g] : make_int4(0, 0, 0, 0);
        int4 rr   = act ? ri[g] : make_int4(0, 0, 0, 0);
        float4 xx = act ? x4[g] : make_float4(1e30f, 1e30f, 1e30f, 1e30f);
        filt_one(ss.x, rr.x, xx.x, lane, s_e4, s_irm, rbase, base);
        filt_one(ss.y, rr.y, xx.y, lane, s_e4, s_irm, rbase, base);
        filt_one(ss.z, rr.z, xx.z, lane, s_e4, s_irm, rbase, base);
        filt_one(ss.w, rr.w, xx.w, lane, s_e4, s_irm, rbase, base);
    }
    // scalar tail (edges beyond n4*4), handled by the last warp
    int tail = n4 << 2;
    if (w == W - 1 && tail < n_edges) {
        int i = tail + lane;
        bool act = i < n_edges;
        int s   = act ? ei[i] : 0;
        int r   = act ? ei[n_edges + i] : 0;
        float xi = act ? x[i] : 1e30f;
        filt_one(s, r, xi, lane, s_e4, s_irm, rbase, base);
    }
    if (lane == 0) g_wcnt[w] = base;
}

// ---------------------------------------------------------------------------
// Stage 3: survivor scatter (no gathers, unconditional RED).
// ---------------------------------------------------------------------------
__global__ void __launch_bounds__(NT, 3)
scatter_kernel(const int* __restrict__ atomic_numbers,
               const float* __restrict__ radii_g,
               float* __restrict__ out,
               int n_edges) {
    extern __shared__ char smem[];
    float4* s_lut = (float4*)smem;                  // NPAIR*8 (8x repl)

    int tid = threadIdx.x, lane = tid & 31, lane8 = tid & 7;

    if (tid < NPAIR) {
        int i = tid / N_ELEMS, j = tid % N_ELEMS;
        int Zi = atomic_numbers[i], Zj = atomic_numbers[j];
        float Zif = (float)Zi, Zjf = (float)Zj;
        float irm = 1.0f / (radii_g[Zi] + radii_g[Zj]);
        float ia  = (powf(Zif, 0.3f) + powf(Zjf, 0.3f))
                    * (1.0f / (0.4543f * 0.529f));
        float pf  = 0.5f * 14.3996f * Zif * Zjf;
        float4 v = make_float4(irm, ia, pf, 0.0f);
        int b = tid << 3;
#pragma unroll
        for (int c = 0; c < 8; c++) s_lut[b + c] = v;
    }
    __syncthreads();

    int n4 = n_edges >> 2;
    int W = (gridDim.x * NT) >> 5;
    int w = (blockIdx.x * NT + tid) >> 5;
    int vpw = (n4 + W - 1) / W;
    int region = vpw * 4 + 32;
    unsigned int rbase = (unsigned int)w * (unsigned int)region;
    unsigned int cnt = g_wcnt[w];

    const float K0 = -3.2f    * 1.44269504f;
    const float K1 = -0.9423f * 1.44269504f;
    const float K2 = -0.4028f * 1.44269504f;
    const float K3 = -0.2016f * 1.44269504f;

    for (unsigned int j = lane; j < cnt; j += 32) {
        uint2 e = g_surv[rbase + j];
        float xi = __uint_as_float(e.x);
        unsigned int r = e.y & 0x00FFFFFFu;
        unsigned int idx = e.y >> 24;
        float4 p = s_lut[(idx << 3) + lane8];   // conflict-free LDS.128

        float rr = xi * p.x;
        float t  = xi * p.y;

        float phi = 0.1818f  * ex2f(K0 * t)
                  + 0.5099f  * ex2f(K1 * t)
                  + 0.2802f  * ex2f(K2 * t)
                  + 0.02817f * ex2f(K3 * t);

        float r2 = rr * rr;
        float r3 = r2 * rr;
        float r6 = r3 * r3;
        float env = fmaf(-28.0f, r6, 1.0f);
        env = fmaf(48.0f, r6 * rr, env);
        env = fmaf(-21.0f, r6 * r2, env);

        float val = p.z * phi * frcpf(xi) * env;
        asm volatile("red.global.add.f32 [%0], %1;"
                     :: "l"(out + r), "f"(val));
    }
}

extern "C" void kernel_launch(void* const* d_in, const int* in_sizes, int n_in,
                              void* d_out, int out_size) {
    const float* x              = (const float*)d_in[0];
    const float* node_attrs     = (const float*)d_in[1];
    const int*   edge_index     = (const int*)  d_in[2];
    const int*   atomic_numbers = (const int*)  d_in[3];
    const float* covalent_radii = (const float*)d_in[4];
    float* out = (float*)d_out;

    int n_edges = in_sizes[0];            // E
    int n_nodes = in_sizes[1] / N_ELEMS;  // N

    {
        int cover = n_nodes > out_size ? n_nodes : out_size;
        int blocks = (cover + 511) / 512;
        node_prep_kernel<<<blocks, 256>>>(node_attrs, out, n_nodes, out_size);
    }

    int smemA = NPAIR * 32 * (int)sizeof(float) + PACKED_N;  // ~63KB
    cudaFuncSetAttribute(filter_kernel,
                         cudaFuncAttributeMaxDynamicSharedMemorySize, smemA);
    filter_kernel<<<EDGE_GRID, NT, smemA>>>(x, edge_index, atomic_numbers,
                                            covalent_radii, n_edges, n_nodes);

    int smemB = NPAIR * 8 * (int)sizeof(float4);             // 12.8KB
    cudaFuncSetAttribute(scatter_kernel,
                         cudaFuncAttributeMaxDynamicSharedMemorySize, smemB);
    scatter_kernel<<<EDGE_GRID, NT, smemB>>>(atomic_numbers, covalent_radii,
                                             out, n_edges);
}

// round 11
// speedup vs baseline: 1.4699x; 1.4699x over previous
#include <cuda_runtime.h>
#include <cuda_bf16.h>

// ZBL basis: per-edge screened Coulomb repulsion with polynomial cutoff,
// scatter-summed into receiver nodes.
//
// Inputs (metadata order):
//   d_in[0]: x               float32 [E, 1]   (E = 3,200,000)
//   d_in[1]: node_attrs      float32 [N, 10]  (N = 100,000)
//   d_in[2]: edge_index      int32   [2, E]
//   d_in[3]: atomic_numbers  int32   [10]
//   d_in[4]: covalent_radii  float32 [119]
// Output: V_ZBL float32 [N]
//
// Fused single-pass design (compaction regressed in R10). HW model: LSU
// wavefront floor (~74 cyc/64 edges: RED sectors 40, gathers 20, LUT 8,
// LDG 6) with a ~1.45x gap attributed to exposed streaming-LDG latency.
// This revision: SOFTWARE PIPELINING — prefetch next iteration's
// (senders, receivers, x) into registers before processing the current one
// (unroll 4, int4/float4 loads), with launch_bounds(512,2) for reg headroom.

#define MAX_NODES 100352            // >= N, even, multiple of 32
#define PACKED_N  (MAX_NODES / 2)   // nibble-packed element table bytes
#define N_ELEMS   10
#define NPAIR     (N_ELEMS * N_ELEMS)
#define NT        512
#define EDGE_GRID 296               // 2 blocks/SM x 148 SMs, one wave

__device__ unsigned char g_e4[PACKED_N];   // 2 nodes/byte: elem idx nibbles

__device__ __forceinline__ float ex2f(float a) {
    float r; asm("ex2.approx.f32 %0, %1;" : "=f"(r) : "f"(a)); return r;
}
__device__ __forceinline__ float frcpf(float a) {
    float r; asm("rcp.approx.f32 %0, %1;" : "=f"(r) : "f"(a)); return r;
}

// Predicated no-return global float add; no memory clobber (write-only out).
__device__ __forceinline__ void red_add_if(float* addr, float val, float rr) {
    asm volatile(
        "{\n\t"
        ".reg .pred p;\n\t"
        "setp.lt.f32 p, %1, 0f3F800000;\n\t"   // rr < 1.0f
        "@p red.global.add.f32 [%0], %2;\n\t"
        "}"
        :: "l"(addr), "f"(rr), "f"(val));
}

// ---------------------------------------------------------------------------
// Node prep: two nodes per thread -> one packed nibble byte; zero the output.
// ---------------------------------------------------------------------------
__global__ void node_prep_kernel(const float* __restrict__ attrs,
                                 float* __restrict__ out,
                                 int n_nodes, int out_n) {
    __shared__ float s[512 * N_ELEMS];
    int base = blockIdx.x * 512;
    int nloc = n_nodes - base;
    if (nloc > 512) nloc = 512;
    if (nloc > 0) {
        int total = nloc * N_ELEMS;
        const float* src = attrs + (size_t)base * N_ELEMS;
        int nv4 = total >> 2;
        const float4* s4 = (const float4*)src;
        float4* d4 = (float4*)s;
        for (int k = threadIdx.x; k < nv4; k += 256) d4[k] = s4[k];
        for (int k = (nv4 << 2) + threadIdx.x; k < total; k += 256)
            s[k] = src[k];
    }
    __syncthreads();

    int t = threadIdx.x;
    int n0 = 2 * t, n1 = 2 * t + 1;
    unsigned char packed = 0;
#pragma unroll
    for (int half = 0; half < 2; half++) {
        int nl = half ? n1 : n0;
        if (nl < nloc) {
            const float* a = s + nl * N_ELEMS;
            int best = 0;
            float bv = a[0];
#pragma unroll
            for (int j = 1; j < N_ELEMS; j++) {
                float v = a[j];
                if (v > bv) { bv = v; best = j; }
            }
            packed |= (unsigned char)(best << (half * 4));
        }
    }
    if (n0 < nloc) g_e4[(base >> 1) + t] = packed;

    int o0 = base + n0, o1 = base + n1;
    if (o0 < out_n) out[o0] = 0.0f;
    if (o1 < out_n) out[o1] = 0.0f;
}

// ---------------------------------------------------------------------------
// Edge kernel
// ---------------------------------------------------------------------------
__device__ __forceinline__ void process_edge(
    int s, int r, float xi, int lane8,
    const unsigned char* __restrict__ s_e4,
    const float4* __restrict__ s_lut,   // [(eu*10+ev)*8 + (lane&7)]
    float* __restrict__ out)
{
    int eu = (s_e4[s >> 1] >> ((s & 1) << 2)) & 15;
    int ev = (s_e4[r >> 1] >> ((r & 1) << 2)) & 15;
    float4 p = s_lut[((eu * N_ELEMS + ev) << 3) + lane8];
    // p = (inv_rmax, invA, pref, 0)

    float rr = xi * p.x;
    float t  = xi * p.y;

    const float K0 = -3.2f    * 1.44269504f;
    const float K1 = -0.9423f * 1.44269504f;
    const float K2 = -0.4028f * 1.44269504f;
    const float K3 = -0.2016f * 1.44269504f;
    float phi = 0.1818f  * ex2f(K0 * t)
              + 0.5099f  * ex2f(K1 * t)
              + 0.2802f  * ex2f(K2 * t)
              + 0.02817f * ex2f(K3 * t);

    // polynomial envelope, p=6: 1 - 28 r^6 + 48 r^7 - 21 r^8
    float r2 = rr * rr;
    float r3 = r2 * rr;
    float r6 = r3 * r3;
    float env = fmaf(-28.0f, r6, 1.0f);
    env = fmaf(48.0f, r6 * rr, env);
    env = fmaf(-21.0f, r6 * r2, env);

    float val = p.z * phi * frcpf(xi) * env;
    red_add_if(out + r, val, rr);
}

__global__ void __launch_bounds__(NT, 2)
edge_kernel(const float* __restrict__ x,
            const int* __restrict__ ei,
            const int* __restrict__ atomic_numbers,
            const float* __restrict__ radii_g,
            float* __restrict__ out,
            int n_edges, int n_nodes) {
    extern __shared__ char smem[];
    float4* s_lut = (float4*)smem;                  // NPAIR*8 float4 = 12.8KB
    unsigned char* s_e4 = (unsigned char*)(s_lut + NPAIR * 8);

    int tid = threadIdx.x;
    int lane8 = tid & 7;

    // 8x-replicated float4 pair LUT (entry e copy c at [e*8+c]): every
    // 8-lane LDS.128 phase spans all 32 banks -> conflict-free.
    if (tid < NPAIR) {
        int i = tid / N_ELEMS, j = tid % N_ELEMS;
        int Zi = atomic_numbers[i], Zj = atomic_numbers[j];
        float Zif = (float)Zi, Zjf = (float)Zj;
        float irm = 1.0f / (radii_g[Zi] + radii_g[Zj]);
        float ia  = (powf(Zif, 0.3f) + powf(Zjf, 0.3f))
                    * (1.0f / (0.4543f * 0.529f));
        float pf  = 0.5f * 14.3996f * Zif * Zjf;
        float4 v = make_float4(irm, ia, pf, 0.0f);
        int b = tid << 3;
#pragma unroll
        for (int c = 0; c < 8; c++) s_lut[b + c] = v;
    }
    // Copy packed nibble table into smem (16B-wide, coalesced, L2-resident)
    {
        const uint4* ge = (const uint4*)g_e4;
        uint4* se = (uint4*)s_e4;
        int nvec = (((n_nodes + 1) >> 1) + 15) >> 4;
        for (int w = tid; w < nvec; w += NT) se[w] = ge[w];
    }
    __syncthreads();

    const int4*   si = (const int4*)ei;
    const int4*   ri = (const int4*)(ei + n_edges);
    const float4* x4 = (const float4*)x;
    int n4 = n_edges >> 2;

    // Block-balanced contiguous chunk; threads stride NT within it.
    int q   = n4 / gridDim.x;
    int rem = n4 - q * gridDim.x;
    int b   = blockIdx.x;
    int start = b * q + (b < rem ? b : rem);
    int end   = start + q + (b < rem ? 1 : 0);

    int g = start + tid;
    // Software pipeline: hold current iteration's data in registers, issue
    // next iteration's loads before processing (hides streaming-LDG latency).
    int4 ss, rr; float4 xx;
    bool act = g < end;
    if (act) { ss = si[g]; rr = ri[g]; xx = x4[g]; }

    while (act) {
        int gn = g + NT;
        bool actn = gn < end;
        int4 ssn, rrn; float4 xxn;
        if (actn) { ssn = si[gn]; rrn = ri[gn]; xxn = x4[gn]; }

        process_edge(ss.x, rr.x, xx.x, lane8, s_e4, s_lut, out);
        process_edge(ss.y, rr.y, xx.y, lane8, s_e4, s_lut, out);
        process_edge(ss.z, rr.z, xx.z, lane8, s_e4, s_lut, out);
        process_edge(ss.w, rr.w, xx.w, lane8, s_e4, s_lut, out);

        ss = ssn; rr = rrn; xx = xxn;
        g = gn; act = actn;
    }

    // scalar tail (n_edges not divisible by 4)
    for (int i = (n4 << 2) + blockIdx.x * NT + tid; i < n_edges;
         i += gridDim.x * NT) {
        process_edge(ei[i], ei[n_edges + i], x[i], lane8, s_e4, s_lut, out);
    }
}

extern "C" void kernel_launch(void* const* d_in, const int* in_sizes, int n_in,
                              void* d_out, int out_size) {
    const float* x              = (const float*)d_in[0];
    const float* node_attrs     = (const float*)d_in[1];
    const int*   edge_index     = (const int*)  d_in[2];
    const int*   atomic_numbers = (const int*)  d_in[3];
    const float* covalent_radii = (const float*)d_in[4];
    float* out = (float*)d_out;

    int n_edges = in_sizes[0];            // E
    int n_nodes = in_sizes[1] / N_ELEMS;  // N

    {
        int cover = n_nodes > out_size ? n_nodes : out_size;
        int blocks = (cover + 511) / 512;
        node_prep_kernel<<<blocks, 256>>>(node_attrs, out, n_nodes, out_size);
    }

    int smem_bytes = NPAIR * 8 * (int)sizeof(float4) + PACKED_N;  // ~63KB
    cudaFuncSetAttribute(edge_kernel,
                         cudaFuncAttributeMaxDynamicSharedMemorySize,
                         smem_bytes);
    edge_kernel<<<EDGE_GRID, NT, smem_bytes>>>(x, edge_index, atomic_numbers,
                                               covalent_radii, out,
                                               n_edges, n_nodes);
}

// round 12
// speedup vs baseline: 1.4743x; 1.0030x over previous
#include <cuda_runtime.h>
#include <cuda_bf16.h>

// ZBL basis: per-edge screened Coulomb repulsion with polynomial cutoff,
// scatter-summed into receiver nodes.
//
// Inputs (metadata order):
//   d_in[0]: x               float32 [E, 1]   (E = 3,200,000)
//   d_in[1]: node_attrs      float32 [N, 10]  (N = 100,000)
//   d_in[2]: edge_index      int32   [2, E]
//   d_in[3]: atomic_numbers  int32   [10]
//   d_in[4]: covalent_radii  float32 [119]
// Output: V_ZBL float32 [N]
//
// node_prep: REGISTER-resident argmax. Each thread owns 2 adjacent nodes
// (80B = 5 float4 direct loads, fully coalesced, full MLP), argmax in regs,
// one nibble-packed byte store. No smem, no syncthreads.
//
// edge: fused single pass (validated R11): software-pipelined streaming
// loads, nibble element table in smem, 8x-replicated float4 pair LUT
// (conflict-free LDS.128), predicated red.global.add.

#define MAX_NODES 100352            // >= N, even, multiple of 32
#define PACKED_N  (MAX_NODES / 2)   // nibble-packed element table bytes
#define N_ELEMS   10
#define NPAIR     (N_ELEMS * N_ELEMS)
#define NT        512
#define EDGE_GRID 296               // 2 blocks/SM x 148 SMs, one wave

__device__ unsigned char g_e4[PACKED_N];   // 2 nodes/byte: elem idx nibbles

__device__ __forceinline__ float ex2f(float a) {
    float r; asm("ex2.approx.f32 %0, %1;" : "=f"(r) : "f"(a)); return r;
}
__device__ __forceinline__ float frcpf(float a) {
    float r; asm("rcp.approx.f32 %0, %1;" : "=f"(r) : "f"(a)); return r;
}

// Predicated no-return global float add; no memory clobber (write-only out).
__device__ __forceinline__ void red_add_if(float* addr, float val, float rr) {
    asm volatile(
        "{\n\t"
        ".reg .pred p;\n\t"
        "setp.lt.f32 p, %1, 0f3F800000;\n\t"   // rr < 1.0f
        "@p red.global.add.f32 [%0], %2;\n\t"
        "}"
        :: "l"(addr), "f"(rr), "f"(val));
}

// ---------------------------------------------------------------------------
// Node prep: 2 adjacent nodes per thread, all in registers.
// ---------------------------------------------------------------------------
__device__ __forceinline__ int argmax10(const float* v) {
    int best = 0;
    float bv = v[0];
#pragma unroll
    for (int j = 1; j < N_ELEMS; j++) {
        if (v[j] > bv) { bv = v[j]; best = j; }
    }
    return best;
}

__global__ void __launch_bounds__(256)
node_prep_kernel(const float* __restrict__ attrs,
                 float* __restrict__ out,
                 int n_nodes, int out_n) {
    int t = blockIdx.x * 256 + threadIdx.x;   // thread owns nodes 2t, 2t+1
    int n0 = 2 * t;

    if (n0 < n_nodes) {
        float v[20];
        const float4* a4 = (const float4*)(attrs + (size_t)n0 * N_ELEMS);
        // 5 independent float4 loads: 80 bytes = 2 nodes x 10 attrs
#pragma unroll
        for (int k = 0; k < 5; k++) {
            float4 q = a4[k];
            v[4 * k + 0] = q.x; v[4 * k + 1] = q.y;
            v[4 * k + 2] = q.z; v[4 * k + 3] = q.w;
        }
        unsigned char packed = (unsigned char)argmax10(v);
        if (n0 + 1 < n_nodes)
            packed |= (unsigned char)(argmax10(v + N_ELEMS) << 4);
        g_e4[t] = packed;
    }

    // zero outputs: 2 per thread
    if (n0 < out_n)     out[n0] = 0.0f;
    if (n0 + 1 < out_n) out[n0 + 1] = 0.0f;
}

// ---------------------------------------------------------------------------
// Edge kernel
// ---------------------------------------------------------------------------
__device__ __forceinline__ void process_edge(
    int s, int r, float xi, int lane8,
    const unsigned char* __restrict__ s_e4,
    const float4* __restrict__ s_lut,   // [(eu*10+ev)*8 + (lane&7)]
    float* __restrict__ out)
{
    int eu = (s_e4[s >> 1] >> ((s & 1) << 2)) & 15;
    int ev = (s_e4[r >> 1] >> ((r & 1) << 2)) & 15;
    float4 p = s_lut[((eu * N_ELEMS + ev) << 3) + lane8];
    // p = (inv_rmax, invA, pref, 0)

    float rr = xi * p.x;
    float t  = xi * p.y;

    const float K0 = -3.2f    * 1.44269504f;
    const float K1 = -0.9423f * 1.44269504f;
    const float K2 = -0.4028f * 1.44269504f;
    const float K3 = -0.2016f * 1.44269504f;
    float phi = 0.1818f  * ex2f(K0 * t)
              + 0.5099f  * ex2f(K1 * t)
              + 0.2802f  * ex2f(K2 * t)
              + 0.02817f * ex2f(K3 * t);

    // polynomial envelope, p=6: 1 - 28 r^6 + 48 r^7 - 21 r^8
    float r2 = rr * rr;
    float r3 = r2 * rr;
    float r6 = r3 * r3;
    float env = fmaf(-28.0f, r6, 1.0f);
    env = fmaf(48.0f, r6 * rr, env);
    env = fmaf(-21.0f, r6 * r2, env);

    float val = p.z * phi * frcpf(xi) * env;
    red_add_if(out + r, val, rr);
}

__global__ void __launch_bounds__(NT, 2)
edge_kernel(const float* __restrict__ x,
            const int* __restrict__ ei,
            const int* __restrict__ atomic_numbers,
            const float* __restrict__ radii_g,
            float* __restrict__ out,
            int n_edges, int n_nodes) {
    extern __shared__ char smem[];
    float4* s_lut = (float4*)smem;                  // NPAIR*8 float4 = 12.8KB
    unsigned char* s_e4 = (unsigned char*)(s_lut + NPAIR * 8);

    int tid = threadIdx.x;
    int lane8 = tid & 7;

    // 8x-replicated float4 pair LUT (entry e copy c at [e*8+c]): every
    // 8-lane LDS.128 phase spans all 32 banks -> conflict-free.
    if (tid < NPAIR) {
        int i = tid / N_ELEMS, j = tid % N_ELEMS;
        int Zi = atomic_numbers[i], Zj = atomic_numbers[j];
        float Zif = (float)Zi, Zjf = (float)Zj;
        float irm = 1.0f / (radii_g[Zi] + radii_g[Zj]);
        float ia  = (powf(Zif, 0.3f) + powf(Zjf, 0.3f))
                    * (1.0f / (0.4543f * 0.529f));
        float pf  = 0.5f * 14.3996f * Zif * Zjf;
        float4 v = make_float4(irm, ia, pf, 0.0f);
        int b = tid << 3;
#pragma unroll
        for (int c = 0; c < 8; c++) s_lut[b + c] = v;
    }
    // Copy packed nibble table into smem (16B-wide, coalesced, L2-resident)
    {
        const uint4* ge = (const uint4*)g_e4;
        uint4* se = (uint4*)s_e4;
        int nvec = (((n_nodes + 1) >> 1) + 15) >> 4;
        for (int w = tid; w < nvec; w += NT) se[w] = ge[w];
    }
    __syncthreads();

    const int4*   si = (const int4*)ei;
    const int4*   ri = (const int4*)(ei + n_edges);
    const float4* x4 = (const float4*)x;
    int n4 = n_edges >> 2;

    // Block-balanced contiguous chunk; threads stride NT within it.
    int q   = n4 / gridDim.x;
    int rem = n4 - q * gridDim.x;
    int b   = blockIdx.x;
    int start = b * q + (b < rem ? b : rem);
    int end   = start + q + (b < rem ? 1 : 0);

    int g = start + tid;
    // Software pipeline: hold current iteration's data in registers, issue
    // next iteration's loads before processing (hides streaming-LDG latency).
    int4 ss, rr; float4 xx;
    bool act = g < end;
    if (act) { ss = si[g]; rr = ri[g]; xx = x4[g]; }

    while (act) {
        int gn = g + NT;
        bool actn = gn < end;
        int4 ssn, rrn; float4 xxn;
        if (actn) { ssn = si[gn]; rrn = ri[gn]; xxn = x4[gn]; }

        process_edge(ss.x, rr.x, xx.x, lane8, s_e4, s_lut, out);
        process_edge(ss.y, rr.y, xx.y, lane8, s_e4, s_lut, out);
        process_edge(ss.z, rr.z, xx.z, lane8, s_e4, s_lut, out);
        process_edge(ss.w, rr.w, xx.w, lane8, s_e4, s_lut, out);

        ss = ssn; rr = rrn; xx = xxn;
        g = gn; act = actn;
    }

    // scalar tail (n_edges not divisible by 4)
    for (int i = (n4 << 2) + blockIdx.x * NT + tid; i < n_edges;
         i += gridDim.x * NT) {
        process_edge(ei[i], ei[n_edges + i], x[i], lane8, s_e4, s_lut, out);
    }
}

extern "C" void kernel_launch(void* const* d_in, const int* in_sizes, int n_in,
                              void* d_out, int out_size) {
    const float* x              = (const float*)d_in[0];
    const float* node_attrs     = (const float*)d_in[1];
    const int*   edge_index     = (const int*)  d_in[2];
    const int*   atomic_numbers = (const int*)  d_in[3];
    const float* covalent_radii = (const float*)d_in[4];
    float* out = (float*)d_out;

    int n_edges = in_sizes[0];            // E
    int n_nodes = in_sizes[1] / N_ELEMS;  // N

    {
        // each thread covers 2 nodes / 2 outputs
        int cover = n_nodes > out_size ? n_nodes : out_size;
        int pairs = (cover + 1) / 2;
        int blocks = (pairs + 255) / 256;
        node_prep_kernel<<<blocks, 256>>>(node_attrs, out, n_nodes, out_size);
    }

    int smem_bytes = NPAIR * 8 * (int)sizeof(float4) + PACKED_N;  // ~63KB
    cudaFuncSetAttribute(edge_kernel,
                         cudaFuncAttributeMaxDynamicSharedMemorySize,
                         smem_bytes);
    edge_kernel<<<EDGE_GRID, NT, smem_bytes>>>(x, edge_index, atomic_numbers,
                                               covalent_radii, out,
                                               n_edges, n_nodes);
}

// round 13
// speedup vs baseline: 1.4901x; 1.0107x over previous
#include <cuda_runtime.h>
#include <cuda_bf16.h>

// ZBL basis: per-edge screened Coulomb repulsion with polynomial cutoff,
// scatter-summed into receiver nodes.
//
// Inputs (metadata order):
//   d_in[0]: x               float32 [E, 1]   (E = 3,200,000)
//   d_in[1]: node_attrs      float32 [N, 10]  (N = 100,000)
//   d_in[2]: edge_index      int32   [2, E]
//   d_in[3]: atomic_numbers  int32   [10]
//   d_in[4]: covalent_radii  float32 [119]
// Output: V_ZBL float32 [N]
//
// node_prep: register-resident argmax (2 nodes/thread, 5x float4 loads),
// nibble-packed element table, fused output zeroing.
//
// edge: fused single pass, software-pipelined streaming loads (hides LDG
// latency, validated R11), nibble table in smem, 8x-replicated float4 pair
// LUT (conflict-free LDS.128), predicated red.global.add.
// NEW: 3 blocks x 512 thr/SM (48 warps; smem 63KB x3 = 189KB fits) to pair
// pipelining WITH higher warp-level latency hiding (R8/R11 each alone were
// partial). launch_bounds(512,3) caps regs at 42.

#define MAX_NODES 100352            // >= N, even, multiple of 32
#define PACKED_N  (MAX_NODES / 2)   // nibble-packed element table bytes
#define N_ELEMS   10
#define NPAIR     (N_ELEMS * N_ELEMS)
#define NT        512
#define EDGE_GRID 444               // 3 blocks/SM x 148 SMs, one wave

__device__ unsigned char g_e4[PACKED_N];   // 2 nodes/byte: elem idx nibbles

__device__ __forceinline__ float ex2f(float a) {
    float r; asm("ex2.approx.f32 %0, %1;" : "=f"(r) : "f"(a)); return r;
}
__device__ __forceinline__ float frcpf(float a) {
    float r; asm("rcp.approx.f32 %0, %1;" : "=f"(r) : "f"(a)); return r;
}

// Predicated no-return global float add; no memory clobber (write-only out).
__device__ __forceinline__ void red_add_if(float* addr, float val, float rr) {
    asm volatile(
        "{\n\t"
        ".reg .pred p;\n\t"
        "setp.lt.f32 p, %1, 0f3F800000;\n\t"   // rr < 1.0f
        "@p red.global.add.f32 [%0], %2;\n\t"
        "}"
        :: "l"(addr), "f"(rr), "f"(val));
}

// ---------------------------------------------------------------------------
// Node prep: 2 adjacent nodes per thread, all in registers.
// ---------------------------------------------------------------------------
__device__ __forceinline__ int argmax10(const float* v) {
    int best = 0;
    float bv = v[0];
#pragma unroll
    for (int j = 1; j < N_ELEMS; j++) {
        if (v[j] > bv) { bv = v[j]; best = j; }
    }
    return best;
}

__global__ void __launch_bounds__(256)
node_prep_kernel(const float* __restrict__ attrs,
                 float* __restrict__ out,
                 int n_nodes, int out_n) {
    int t = blockIdx.x * 256 + threadIdx.x;   // thread owns nodes 2t, 2t+1
    int n0 = 2 * t;

    if (n0 < n_nodes) {
        float v[20];
        const float4* a4 = (const float4*)(attrs + (size_t)n0 * N_ELEMS);
#pragma unroll
        for (int k = 0; k < 5; k++) {
            float4 q = a4[k];
            v[4 * k + 0] = q.x; v[4 * k + 1] = q.y;
            v[4 * k + 2] = q.z; v[4 * k + 3] = q.w;
        }
        unsigned char packed = (unsigned char)argmax10(v);
        if (n0 + 1 < n_nodes)
            packed |= (unsigned char)(argmax10(v + N_ELEMS) << 4);
        g_e4[t] = packed;
    }

    if (n0 < out_n)     out[n0] = 0.0f;
    if (n0 + 1 < out_n) out[n0 + 1] = 0.0f;
}

// ---------------------------------------------------------------------------
// Edge kernel
// ---------------------------------------------------------------------------
__device__ __forceinline__ void process_edge(
    int s, int r, float xi, int lane8,
    const unsigned char* __restrict__ s_e4,
    const float4* __restrict__ s_lut,   // [(eu*10+ev)*8 + (lane&7)]
    float* __restrict__ out)
{
    int eu = (s_e4[s >> 1] >> ((s & 1) << 2)) & 15;
    int ev = (s_e4[r >> 1] >> ((r & 1) << 2)) & 15;
    float4 p = s_lut[((eu * N_ELEMS + ev) << 3) + lane8];
    // p = (inv_rmax, invA, pref, 0)

    float rr = xi * p.x;
    float t  = xi * p.y;

    const float K0 = -3.2f    * 1.44269504f;
    const float K1 = -0.9423f * 1.44269504f;
    const float K2 = -0.4028f * 1.44269504f;
    const float K3 = -0.2016f * 1.44269504f;
    float phi = 0.1818f  * ex2f(K0 * t)
              + 0.5099f  * ex2f(K1 * t)
              + 0.2802f  * ex2f(K2 * t)
              + 0.02817f * ex2f(K3 * t);

    // polynomial envelope, p=6: 1 - 28 r^6 + 48 r^7 - 21 r^8
    float r2 = rr * rr;
    float r3 = r2 * rr;
    float r6 = r3 * r3;
    float env = fmaf(-28.0f, r6, 1.0f);
    env = fmaf(48.0f, r6 * rr, env);
    env = fmaf(-21.0f, r6 * r2, env);

    float val = p.z * phi * frcpf(xi) * env;
    red_add_if(out + r, val, rr);
}

__global__ void __launch_bounds__(NT, 3)
edge_kernel(const float* __restrict__ x,
            const int* __restrict__ ei,
            const int* __restrict__ atomic_numbers,
            const float* __restrict__ radii_g,
            float* __restrict__ out,
            int n_edges, int n_nodes) {
    extern __shared__ char smem[];
    float4* s_lut = (float4*)smem;                  // NPAIR*8 float4 = 12.8KB
    unsigned char* s_e4 = (unsigned char*)(s_lut + NPAIR * 8);

    int tid = threadIdx.x;
    int lane8 = tid & 7;

    // 8x-replicated float4 pair LUT (entry e copy c at [e*8+c]): every
    // 8-lane LDS.128 phase spans all 32 banks -> conflict-free.
    if (tid < NPAIR) {
        int i = tid / N_ELEMS, j = tid % N_ELEMS;
        int Zi = atomic_numbers[i], Zj = atomic_numbers[j];
        float Zif = (float)Zi, Zjf = (float)Zj;
        float irm = 1.0f / (radii_g[Zi] + radii_g[Zj]);
        float ia  = (powf(Zif, 0.3f) + powf(Zjf, 0.3f))
                    * (1.0f / (0.4543f * 0.529f));
        float pf  = 0.5f * 14.3996f * Zif * Zjf;
        float4 v = make_float4(irm, ia, pf, 0.0f);
        int b = tid << 3;
#pragma unroll
        for (int c = 0; c < 8; c++) s_lut[b + c] = v;
    }
    // Copy packed nibble table into smem (16B-wide, coalesced, L2-resident)
    {
        const uint4* ge = (const uint4*)g_e4;
        uint4* se = (uint4*)s_e4;
        int nvec = (((n_nodes + 1) >> 1) + 15) >> 4;
        for (int w = tid; w < nvec; w += NT) se[w] = ge[w];
    }
    __syncthreads();

    const int4*   si = (const int4*)ei;
    const int4*   ri = (const int4*)(ei + n_edges);
    const float4* x4 = (const float4*)x;
    int n4 = n_edges >> 2;

    // Block-balanced contiguous chunk; threads stride NT within it.
    int q   = n4 / gridDim.x;
    int rem = n4 - q * gridDim.x;
    int b   = blockIdx.x;
    int start = b * q + (b < rem ? b : rem);
    int end   = start + q + (b < rem ? 1 : 0);

    int g = start + tid;
    // Software pipeline: hold current iteration's data in registers, issue
    // next iteration's loads before processing (hides streaming-LDG latency).
    int4 ss, rr; float4 xx;
    bool act = g < end;
    if (act) { ss = si[g]; rr = ri[g]; xx = x4[g]; }

    while (act) {
        int gn = g + NT;
        bool actn = gn < end;
        int4 ssn, rrn; float4 xxn;
        if (actn) { ssn = si[gn]; rrn = ri[gn]; xxn = x4[gn]; }

        process_edge(ss.x, rr.x, xx.x, lane8, s_e4, s_lut, out);
        process_edge(ss.y, rr.y, xx.y, lane8, s_e4, s_lut, out);
        process_edge(ss.z, rr.z, xx.z, lane8, s_e4, s_lut, out);
        process_edge(ss.w, rr.w, xx.w, lane8, s_e4, s_lut, out);

        ss = ssn; rr = rrn; xx = xxn;
        g = gn; act = actn;
    }

    // scalar tail (n_edges not divisible by 4)
    for (int i = (n4 << 2) + blockIdx.x * NT + tid; i < n_edges;
         i += gridDim.x * NT) {
        process_edge(ei[i], ei[n_edges + i], x[i], lane8, s_e4, s_lut, out);
    }
}

extern "C" void kernel_launch(void* const* d_in, const int* in_sizes, int n_in,
                              void* d_out, int out_size) {
    const float* x              = (const float*)d_in[0];
    const float* node_attrs     = (const float*)d_in[1];
    const int*   edge_index     = (const int*)  d_in[2];
    const int*   atomic_numbers = (const int*)  d_in[3];
    const float* covalent_radii = (const float*)d_in[4];
    float* out = (float*)d_out;

    int n_edges = in_sizes[0];            // E
    int n_nodes = in_sizes[1] / N_ELEMS;  // N

    {
        int cover = n_nodes > out_size ? n_nodes : out_size;
        int pairs = (cover + 1) / 2;
        int blocks = (pairs + 255) / 256;
        node_prep_kernel<<<blocks, 256>>>(node_attrs, out, n_nodes, out_size);
    }

    int smem_bytes = NPAIR * 8 * (int)sizeof(float4) + PACKED_N;  // ~63KB
    cudaFuncSetAttribute(edge_kernel,
                         cudaFuncAttributeMaxDynamicSharedMemorySize,
                         smem_bytes);
    // THREE blocks/SM x 148 SMs, one full wave
    edge_kernel<<<EDGE_GRID, NT, smem_bytes>>>(x, edge_index, atomic_numbers,
                                               covalent_radii, out,
                                               n_edges, n_nodes);
}